// round 1
// baseline (speedup 1.0000x reference)
#include <cuda_runtime.h>
#include <cuda_bf16.h>

// Problem constants (fixed shapes per reference setup_inputs)
#define B_  16
#define C_  306
#define T_  4000
#define M_  128
#define TN  128     // T-tile
#define KB  16      // K-chunk

// Scratch: normalized channel weights, layout [b][c][m] (m contiguous)
__device__ float g_w[B_ * C_ * M_];

// inv = 1/(2*sigma^2), sigma = 0.1 * 2^i
#define INV0 50.0f
#define INV1 12.5f
#define INV2 3.125f

// ---------------------------------------------------------------------------
// Kernel 1: per-(b,m) gate weights + normalization over C.
// grid = B_*M_ blocks, 320 threads (>= C_), each thread handles one channel c.
// ---------------------------------------------------------------------------
__global__ void __launch_bounds__(320) mrm_weights_kernel(
    const float* __restrict__ pos,      // [B, C, 2]
    const float* __restrict__ tpos,     // [M, 2]
    const float* __restrict__ w1,       // [3, 32] row-major
    const float* __restrict__ b1,       // [32]
    const float* __restrict__ w2,       // [32]
    const float* __restrict__ b2)       // [1]
{
    __shared__ float s_w1[96];
    __shared__ float s_b1[32];
    __shared__ float s_w2[32];
    __shared__ float warp_sums[10];
    __shared__ float s_total;

    const int bm = blockIdx.x;
    const int b  = bm / M_;
    const int m  = bm % M_;
    const int tid = threadIdx.x;

    if (tid < 96) s_w1[tid] = w1[tid];
    if (tid >= 96 && tid < 128) s_b1[tid - 96] = b1[tid - 96];
    if (tid >= 128 && tid < 160) s_w2[tid - 128] = w2[tid - 128];
    __syncthreads();

    const float txp = tpos[2 * m + 0];
    const float typ = tpos[2 * m + 1];
    const float bias2 = b2[0];

    float wv = 0.0f;
    const int c = tid;
    if (c < C_) {
        const float px = pos[((size_t)b * C_ + c) * 2 + 0];
        const float py = pos[((size_t)b * C_ + c) * 2 + 1];
        const float dx = px - txp;
        const float dy = py - typ;
        const float d2 = dx * dx + dy * dy;
        const float s0 = __expf(-d2 * INV0);
        const float s1 = __expf(-d2 * INV1);
        const float s2 = __expf(-d2 * INV2);
        float acc = bias2;
#pragma unroll
        for (int j = 0; j < 32; j++) {
            float h = s_b1[j];
            h = fmaf(s0, s_w1[j], h);
            h = fmaf(s1, s_w1[32 + j], h);
            h = fmaf(s2, s_w1[64 + j], h);
            h = fmaxf(h, 0.0f);
            acc = fmaf(h, s_w2[j], acc);
        }
        wv = acc;
    }

    // block reduce sum over C (320 threads, 10 warps)
    float v = wv;
#pragma unroll
    for (int o = 16; o > 0; o >>= 1) v += __shfl_down_sync(0xffffffffu, v, o);
    if ((tid & 31) == 0) warp_sums[tid >> 5] = v;
    __syncthreads();
    if (tid == 0) {
        float s = 0.0f;
#pragma unroll
        for (int i = 0; i < 10; i++) s += warp_sums[i];
        s_total = s + 1e-8f;
    }
    __syncthreads();

    if (c < C_) {
        g_w[((size_t)b * C_ + c) * M_ + m] = wv / s_total;
    }
}

// ---------------------------------------------------------------------------
// Kernel 2: out[b,m,t] = sum_c g_w[b,c,m] * x[b,c,t]
// Per batch: [128 x 306] @ [306 x 4000]. Tile 128(M) x 128(T), K-chunk 16.
// 256 threads, each computes an 8x8 micro-tile.
// ---------------------------------------------------------------------------
__global__ void __launch_bounds__(256, 2) mrm_gemm_kernel(
    const float* __restrict__ x,   // [B, C, T]
    float* __restrict__ out)       // [B, M, T]
{
    __shared__ __align__(16) float Ws[KB][M_];   // 8 KB
    __shared__ __align__(16) float Xs[KB][TN];   // 8 KB

    const int b  = blockIdx.y;
    const int t0 = blockIdx.x * TN;
    const int tid = threadIdx.x;

    const float* W = g_w + (size_t)b * C_ * M_;
    const float* X = x   + (size_t)b * C_ * T_;

    const int tcol = tid & 15;   // t direction
    const int trow = tid >> 4;   // m direction

    float acc[8][8];
#pragma unroll
    for (int i = 0; i < 8; i++)
#pragma unroll
        for (int j = 0; j < 8; j++) acc[i][j] = 0.0f;

    for (int k0 = 0; k0 < C_; k0 += KB) {
        // Load W tile: KB rows x 128 floats = 512 float4, 2 per thread
#pragma unroll
        for (int i = 0; i < 2; i++) {
            const int idx = tid + i * 256;     // float4 index 0..511
            const int r  = idx >> 5;           // row within chunk
            const int cc = idx & 31;           // float4 col
            const int k  = k0 + r;
            float4 v = make_float4(0.f, 0.f, 0.f, 0.f);
            if (k < C_) v = ((const float4*)(W + (size_t)k * M_))[cc];
            ((float4*)&Ws[r][0])[cc] = v;
        }
        // Load X tile: KB rows x 128 floats
#pragma unroll
        for (int i = 0; i < 2; i++) {
            const int idx = tid + i * 256;
            const int r  = idx >> 5;
            const int cc = idx & 31;
            const int k  = k0 + r;
            const int t  = t0 + cc * 4;
            float4 v = make_float4(0.f, 0.f, 0.f, 0.f);
            if (k < C_ && t + 3 < T_) v = *(const float4*)(X + (size_t)k * T_ + t);
            ((float4*)&Xs[r][0])[cc] = v;
        }
        __syncthreads();

#pragma unroll
        for (int k = 0; k < KB; k++) {
            float a[8], bb[8];
            const float4* WsV = (const float4*)&Ws[k][0];
            const float4* XsV = (const float4*)&Xs[k][0];
            float4 a0 = WsV[trow * 2 + 0];
            float4 a1 = WsV[trow * 2 + 1];
            float4 b0 = XsV[tcol * 2 + 0];
            float4 b1 = XsV[tcol * 2 + 1];
            a[0]=a0.x; a[1]=a0.y; a[2]=a0.z; a[3]=a0.w;
            a[4]=a1.x; a[5]=a1.y; a[6]=a1.z; a[7]=a1.w;
            bb[0]=b0.x; bb[1]=b0.y; bb[2]=b0.z; bb[3]=b0.w;
            bb[4]=b1.x; bb[5]=b1.y; bb[6]=b1.z; bb[7]=b1.w;
#pragma unroll
            for (int i = 0; i < 8; i++)
#pragma unroll
                for (int j = 0; j < 8; j++)
                    acc[i][j] = fmaf(a[i], bb[j], acc[i][j]);
        }
        __syncthreads();
    }

    // Store 8x8 micro-tile
    const int mbase = trow * 8;
    const int tbase = t0 + tcol * 8;
#pragma unroll
    for (int i = 0; i < 8; i++) {
        const int m = mbase + i;
        float* o = out + ((size_t)b * M_ + m) * T_ + tbase;
#pragma unroll
        for (int j = 0; j < 8; j += 4) {
            if (tbase + j + 3 < T_) {
                *(float4*)(o + j) = make_float4(acc[i][j], acc[i][j+1],
                                                acc[i][j+2], acc[i][j+3]);
            } else {
#pragma unroll
                for (int q = 0; q < 4; q++)
                    if (tbase + j + q < T_) o[j + q] = acc[i][j + q];
            }
        }
    }
}

extern "C" void kernel_launch(void* const* d_in, const int* in_sizes, int n_in,
                              void* d_out, int out_size) {
    const float* x    = (const float*)d_in[0];  // [16,306,4000]
    const float* pos  = (const float*)d_in[1];  // [16,306,2]
    const float* tpos = (const float*)d_in[2];  // [128,2]
    const float* w1   = (const float*)d_in[3];  // [3,32]
    const float* b1   = (const float*)d_in[4];  // [32]
    const float* w2   = (const float*)d_in[5];  // [32,1]
    const float* b2   = (const float*)d_in[6];  // [1]
    float* out = (float*)d_out;

    mrm_weights_kernel<<<B_ * M_, 320>>>(pos, tpos, w1, b1, w2, b2);

    dim3 grid((T_ + TN - 1) / TN, B_);   // 32 x 16
    mrm_gemm_kernel<<<grid, 256>>>(x, out);
}

// round 3
// speedup vs baseline: 1.6016x; 1.6016x over previous
#include <cuda_runtime.h>
#include <cuda_bf16.h>
#include <cstdint>

// ---------------------------------------------------------------------------
// Problem constants
// ---------------------------------------------------------------------------
#define B_   16
#define C_   306
#define CP_  320      // C padded to multiple of 32
#define T_   4000
#define M_   128
#define TN_  128      // t-tile per CTA
#define KC_  32       // K chunk
#define NCHUNK 10     // CP_/KC_

#define INV0 50.0f
#define INV1 12.5f
#define INV2 3.125f

// smem tile row stride in bytes (64B data + 16B pad -> conflict-free ldmatrix)
#define RS 80

// Scratch: channel weights as split bf16, layout [b][m][c] (c contiguous, padded)
__device__ __align__(16) __nv_bfloat16 g_w_hi[B_ * M_ * CP_];
__device__ __align__(16) __nv_bfloat16 g_w_lo[B_ * M_ * CP_];

__device__ __forceinline__ uint32_t smem_u32(const void* p) {
    uint32_t a;
    asm("{ .reg .u64 t; cvta.to.shared.u64 t, %1; cvt.u32.u64 %0, t; }" : "=r"(a) : "l"(p));
    return a;
}

#define LDSM4(r, addr) \
    asm volatile("ldmatrix.sync.aligned.m8n8.x4.shared.b16 {%0,%1,%2,%3}, [%4];" \
        : "=r"((r)[0]), "=r"((r)[1]), "=r"((r)[2]), "=r"((r)[3]) : "r"(addr))

#define STS16(addr, v) \
    asm volatile("st.shared.v4.b32 [%0], {%1,%2,%3,%4};" \
        :: "r"(addr), "r"((v).x), "r"((v).y), "r"((v).z), "r"((v).w) : "memory")

#define MMA_BF16(c, a, b0, b1) \
    asm volatile("mma.sync.aligned.m16n8k16.row.col.f32.bf16.bf16.f32 " \
        "{%0,%1,%2,%3}, {%4,%5,%6,%7}, {%8,%9}, {%0,%1,%2,%3};" \
        : "+f"((c)[0]), "+f"((c)[1]), "+f"((c)[2]), "+f"((c)[3]) \
        : "r"((a)[0]), "r"((a)[1]), "r"((a)[2]), "r"((a)[3]), "r"(b0), "r"(b1))

// ---------------------------------------------------------------------------
// Kernel 1: gate weights -> normalized -> split bf16 -> g_w_hi/lo [b][m][c]
// ---------------------------------------------------------------------------
__global__ void __launch_bounds__(CP_) mrm_weights_kernel(
    const float* __restrict__ pos, const float* __restrict__ tpos,
    const float* __restrict__ w1, const float* __restrict__ b1,
    const float* __restrict__ w2, const float* __restrict__ b2)
{
    __shared__ float s_w1[96], s_b1[32], s_w2[32];
    __shared__ float warp_sums[10];
    __shared__ float s_total;

    const int bm = blockIdx.x;
    const int b = bm / M_, m = bm % M_;
    const int tid = threadIdx.x;

    if (tid < 96) s_w1[tid] = w1[tid];
    else if (tid < 128) s_b1[tid - 96] = b1[tid - 96];
    else if (tid < 160) s_w2[tid - 128] = w2[tid - 128];
    __syncthreads();

    const float txp = tpos[2 * m], typ = tpos[2 * m + 1];
    const float bias2 = b2[0];

    float wv = 0.0f;
    const int c = tid;
    if (c < C_) {
        const float px = pos[((size_t)b * C_ + c) * 2 + 0];
        const float py = pos[((size_t)b * C_ + c) * 2 + 1];
        const float dx = px - txp, dy = py - typ;
        const float d2 = dx * dx + dy * dy;
        const float s0 = __expf(-d2 * INV0);
        const float s1 = __expf(-d2 * INV1);
        const float s2 = __expf(-d2 * INV2);
        float acc = bias2;
#pragma unroll
        for (int j = 0; j < 32; j++) {
            float h = s_b1[j];
            h = fmaf(s0, s_w1[j], h);
            h = fmaf(s1, s_w1[32 + j], h);
            h = fmaf(s2, s_w1[64 + j], h);
            h = fmaxf(h, 0.0f);
            acc = fmaf(h, s_w2[j], acc);
        }
        wv = acc;
    }

    float v = wv;
#pragma unroll
    for (int o = 16; o > 0; o >>= 1) v += __shfl_down_sync(0xffffffffu, v, o);
    if ((tid & 31) == 0) warp_sums[tid >> 5] = v;
    __syncthreads();
    if (tid == 0) {
        float s = 0.0f;
#pragma unroll
        for (int i = 0; i < 10; i++) s += warp_sums[i];
        s_total = s + 1e-8f;
    }
    __syncthreads();

    float wn = (c < C_) ? (wv / s_total) : 0.0f;
    __nv_bfloat16 h = __float2bfloat16(wn);
    __nv_bfloat16 l = __float2bfloat16(wn - __bfloat162float(h));
    const size_t o = ((size_t)b * M_ + m) * CP_ + c;
    g_w_hi[o] = h;
    g_w_lo[o] = l;
}

// ---------------------------------------------------------------------------
// Kernel 2: mma.sync (HMMA) split-bf16 GEMM.
// CTA = (t-tile, b): D[128 m][128 t] = sum_k W[m,k] * X[k,t]
// 8 warps as 2(m) x 4(n); warp tile 64(m) x 32(t).
// ---------------------------------------------------------------------------
__global__ void __launch_bounds__(256, 1) mrm_hmma_kernel(
    const float* __restrict__ x, float* __restrict__ out)
{
    // 4 tiles of 128 rows x RS bytes: A_hi, A_lo, B_hi, B_lo
    __shared__ __align__(16) char stile[4 * 128 * RS];
    const uint32_t sAh = smem_u32(stile);
    const uint32_t sAl = sAh + 128 * RS;
    const uint32_t sBh = sAl + 128 * RS;
    const uint32_t sBl = sBh + 128 * RS;

    const int b   = blockIdx.y;
    const int t0  = blockIdx.x * TN_;
    const int tid = threadIdx.x;
    const int lane = tid & 31;
    const int wid  = tid >> 5;
    const int warp_m = wid >> 2;        // 0..1
    const int warp_n = wid & 3;         // 0..3
    const int tl = tid & 127;           // loader row (m for A, t for B)
    const int kg = tid >> 7;            // 0/1

    const int tg  = t0 + tl;
    const bool tok = tg < T_;
    const float* xb = x + (size_t)b * C_ * T_;

    // ldmatrix per-thread source addresses
    const int lr  = lane & 7;
    const int sel = lane >> 3;          // 0..3
    // A: mat0 rows m0..7 @k0 | mat1 rows m0+8.. @k0 | mat2 rows m0..7 @k8 | mat3 rows+8 @k8
    const int a_row = warp_m * 64 + lr + (sel & 1) * 8;
    const int a_col = (sel >> 1) * 16;                  // bytes
    // B: mat0 rows n0..7 @k0 | mat1 rows n0..7 @k8 | mat2 rows n0+8 @k0 | mat3 rows n0+8 @k8
    const int b_row = warp_n * 32 + lr + (sel >> 1) * 8;
    const int b_col = (sel & 1) * 16;                   // bytes

    float acc[4][4][4];
#pragma unroll
    for (int i = 0; i < 4; i++)
#pragma unroll
        for (int j = 0; j < 4; j++)
#pragma unroll
            for (int q = 0; q < 4; q++) acc[i][j][q] = 0.0f;

    // prefetch registers
    uint4 pa[4];
    float pb[16];

    // A source row pointer (thread tl = m row; kg selects hi/lo matrix)
    const __nv_bfloat16* arow = (kg ? g_w_lo : g_w_hi) + ((size_t)b * M_ + tl) * CP_;

    // ---- prefetch chunk 0
    {
        const uint4* asrc = (const uint4*)(arow);
        pa[0] = asrc[0]; pa[1] = asrc[1]; pa[2] = asrc[2]; pa[3] = asrc[3];
        const float* xc = xb + (size_t)(kg * 16) * T_ + tg;
#pragma unroll
        for (int j = 0; j < 16; j++)
            pb[j] = tok ? __ldg(xc + (size_t)j * T_) : 0.0f;
    }

    for (int i = 0; i < NCHUNK; i++) {
        // ---- convert + STS current chunk
        {
            const uint32_t adst = (kg ? sAl : sAh) + tl * RS;
            STS16(adst +  0, pa[0]);
            STS16(adst + 16, pa[1]);
            STS16(adst + 32, pa[2]);
            STS16(adst + 48, pa[3]);

            uint32_t hi[8], lo[8];
#pragma unroll
            for (int q = 0; q < 8; q++) {
                float v0 = pb[2 * q], v1 = pb[2 * q + 1];
                __nv_bfloat16 h0 = __float2bfloat16(v0);
                __nv_bfloat16 h1 = __float2bfloat16(v1);
                float l0 = v0 - __bfloat162float(h0);
                float l1 = v1 - __bfloat162float(h1);
                hi[q] = (uint32_t)__bfloat16_as_ushort(h0)
                      | ((uint32_t)__bfloat16_as_ushort(h1) << 16);
                __nv_bfloat16 g0 = __float2bfloat16(l0);
                __nv_bfloat16 g1 = __float2bfloat16(l1);
                lo[q] = (uint32_t)__bfloat16_as_ushort(g0)
                      | ((uint32_t)__bfloat16_as_ushort(g1) << 16);
            }
            const uint32_t boff = tl * RS + kg * 32;
            uint4 vh0 = make_uint4(hi[0], hi[1], hi[2], hi[3]);
            uint4 vh1 = make_uint4(hi[4], hi[5], hi[6], hi[7]);
            uint4 vl0 = make_uint4(lo[0], lo[1], lo[2], lo[3]);
            uint4 vl1 = make_uint4(lo[4], lo[5], lo[6], lo[7]);
            STS16(sBh + boff,      vh0);
            STS16(sBh + boff + 16, vh1);
            STS16(sBl + boff,      vl0);
            STS16(sBl + boff + 16, vl1);
        }
        __syncthreads();

        // ---- issue gmem prefetch for next chunk (hidden behind MMA block)
        if (i + 1 < NCHUNK) {
            const int k0n = (i + 1) * KC_;
            const uint4* asrc = (const uint4*)(arow + k0n);
            pa[0] = asrc[0]; pa[1] = asrc[1]; pa[2] = asrc[2]; pa[3] = asrc[3];
            const float* xc = xb + (size_t)(k0n + kg * 16) * T_ + tg;
            const int kbase = k0n + kg * 16;
#pragma unroll
            for (int j = 0; j < 16; j++)
                pb[j] = (tok && (kbase + j) < C_) ? __ldg(xc + (size_t)j * T_) : 0.0f;
        }

        // ---- MMA over the 2 k16 steps of this chunk
#pragma unroll
        for (int ks = 0; ks < 2; ks++) {
            uint32_t af[4][4], bh[2][4], bl[2][4];
            const uint32_t acol = ks * 32 + a_col;
            const uint32_t bcol = ks * 32 + b_col;
#pragma unroll
            for (int g = 0; g < 2; g++) {
                LDSM4(bh[g], sBh + (uint32_t)(b_row + g * 16) * RS + bcol);
                LDSM4(bl[g], sBl + (uint32_t)(b_row + g * 16) * RS + bcol);
            }
#pragma unroll
            for (int mf = 0; mf < 4; mf++)
                LDSM4(af[mf], sAh + (uint32_t)(a_row + mf * 16) * RS + acol);
            // hi*hi and hi*lo
#pragma unroll
            for (int mf = 0; mf < 4; mf++)
#pragma unroll
                for (int nf = 0; nf < 4; nf++) {
                    const int g = nf >> 1, s2 = (nf & 1) * 2;
                    MMA_BF16(acc[mf][nf], af[mf], bh[g][s2], bh[g][s2 + 1]);
                    MMA_BF16(acc[mf][nf], af[mf], bl[g][s2], bl[g][s2 + 1]);
                }
            // lo*hi
#pragma unroll
            for (int mf = 0; mf < 4; mf++)
                LDSM4(af[mf], sAl + (uint32_t)(a_row + mf * 16) * RS + acol);
#pragma unroll
            for (int mf = 0; mf < 4; mf++)
#pragma unroll
                for (int nf = 0; nf < 4; nf++) {
                    const int g = nf >> 1, s2 = (nf & 1) * 2;
                    MMA_BF16(acc[mf][nf], af[mf], bh[g][s2], bh[g][s2 + 1]);
                }
        }
        __syncthreads();
    }

    // ---- epilogue: direct global stores (warp n-tiles are 32-wide; T_ % 32 == 0)
    if (t0 + warp_n * 32 < T_) {
        const int mb = warp_m * 64 + (lane >> 2);
        const int cb = t0 + warp_n * 32 + (lane & 3) * 2;
#pragma unroll
        for (int mf = 0; mf < 4; mf++) {
#pragma unroll
            for (int nf = 0; nf < 4; nf++) {
                const int m = mb + mf * 16;
                const int t = cb + nf * 8;
                float* o0 = out + ((size_t)b * M_ + m) * T_ + t;
                float* o1 = out + ((size_t)b * M_ + m + 8) * T_ + t;
                *(float2*)o0 = make_float2(acc[mf][nf][0], acc[mf][nf][1]);
                *(float2*)o1 = make_float2(acc[mf][nf][2], acc[mf][nf][3]);
            }
        }
    }
}

// ---------------------------------------------------------------------------
extern "C" void kernel_launch(void* const* d_in, const int* in_sizes, int n_in,
                              void* d_out, int out_size) {
    const float* x    = (const float*)d_in[0];
    const float* pos  = (const float*)d_in[1];
    const float* tpos = (const float*)d_in[2];
    const float* w1   = (const float*)d_in[3];
    const float* b1   = (const float*)d_in[4];
    const float* w2   = (const float*)d_in[5];
    const float* b2   = (const float*)d_in[6];
    float* out = (float*)d_out;

    mrm_weights_kernel<<<B_ * M_, CP_>>>(pos, tpos, w1, b1, w2, b2);

    dim3 grid((T_ + TN_ - 1) / TN_, B_);   // 32 x 16 = 512 CTAs
    mrm_hmma_kernel<<<grid, 256>>>(x, out);
}

// round 4
// speedup vs baseline: 2.2473x; 1.4032x over previous
#include <cuda_runtime.h>
#include <cuda_bf16.h>
#include <cstdint>

// ---------------------------------------------------------------------------
// Problem constants
// ---------------------------------------------------------------------------
#define B_   16
#define C_   306
#define CP_  320      // C padded to multiple of 32
#define T_   4000
#define M_   128
#define TN_  128      // t-tile per CTA
#define KC_  32       // K chunk
#define NCHUNK 10     // CP_/KC_

#define INV0 50.0f
#define INV1 12.5f
#define INV2 3.125f

// smem tile row stride in bytes (64B data + 16B pad -> conflict-free ldmatrix)
#define RS 80

// SMEM layout (bytes, dynamic)
#define OFF_AH(s) ((s) * 10240)                 // A_hi stages: 0, 10240
#define OFF_AL(s) (20480 + (s) * 10240)         // A_lo stages
#define OFF_XF(s) (40960 + (s) * 16384)         // fp32 X staging
#define OFF_BH    73728
#define OFF_BL    83968
#define SMEM_TOTAL 94208

// Scratch: channel weights as split bf16, layout [b][m][c] (c contiguous, padded)
__device__ __align__(16) __nv_bfloat16 g_w_hi[B_ * M_ * CP_];
__device__ __align__(16) __nv_bfloat16 g_w_lo[B_ * M_ * CP_];

__device__ __forceinline__ uint32_t smem_u32(const void* p) {
    uint32_t a;
    asm("{ .reg .u64 t; cvta.to.shared.u64 t, %1; cvt.u32.u64 %0, t; }" : "=r"(a) : "l"(p));
    return a;
}

#define LDSM4(r, addr) \
    asm volatile("ldmatrix.sync.aligned.m8n8.x4.shared.b16 {%0,%1,%2,%3}, [%4];" \
        : "=r"((r)[0]), "=r"((r)[1]), "=r"((r)[2]), "=r"((r)[3]) : "r"(addr))

#define STS16(addr, v) \
    asm volatile("st.shared.v4.b32 [%0], {%1,%2,%3,%4};" \
        :: "r"(addr), "r"((v).x), "r"((v).y), "r"((v).z), "r"((v).w) : "memory")

#define CP16(dst, src, sz) \
    asm volatile("cp.async.cg.shared.global [%0], [%1], 16, %2;" \
        :: "r"(dst), "l"(src), "r"(sz) : "memory")

#define CP_COMMIT() asm volatile("cp.async.commit_group;" ::: "memory")

#define MMA_BF16(c, a, b0, b1) \
    asm volatile("mma.sync.aligned.m16n8k16.row.col.f32.bf16.bf16.f32 " \
        "{%0,%1,%2,%3}, {%4,%5,%6,%7}, {%8,%9}, {%0,%1,%2,%3};" \
        : "+f"((c)[0]), "+f"((c)[1]), "+f"((c)[2]), "+f"((c)[3]) \
        : "r"((a)[0]), "r"((a)[1]), "r"((a)[2]), "r"((a)[3]), "r"(b0), "r"(b1))

// ---------------------------------------------------------------------------
// Kernel 1: gate weights -> normalized -> split bf16 -> g_w_hi/lo [b][m][c]
// (writes zeros into the C-padding so GEMM never reads garbage)
// ---------------------------------------------------------------------------
__global__ void __launch_bounds__(CP_) mrm_weights_kernel(
    const float* __restrict__ pos, const float* __restrict__ tpos,
    const float* __restrict__ w1, const float* __restrict__ b1,
    const float* __restrict__ w2, const float* __restrict__ b2)
{
    __shared__ float s_w1[96], s_b1[32], s_w2[32];
    __shared__ float warp_sums[10];
    __shared__ float s_total;

    const int bm = blockIdx.x;
    const int b = bm / M_, m = bm % M_;
    const int tid = threadIdx.x;

    if (tid < 96) s_w1[tid] = w1[tid];
    else if (tid < 128) s_b1[tid - 96] = b1[tid - 96];
    else if (tid < 160) s_w2[tid - 128] = w2[tid - 128];
    __syncthreads();

    const float txp = tpos[2 * m], typ = tpos[2 * m + 1];
    const float bias2 = b2[0];

    float wv = 0.0f;
    const int c = tid;
    if (c < C_) {
        const float px = pos[((size_t)b * C_ + c) * 2 + 0];
        const float py = pos[((size_t)b * C_ + c) * 2 + 1];
        const float dx = px - txp, dy = py - typ;
        const float d2 = dx * dx + dy * dy;
        const float s0 = __expf(-d2 * INV0);
        const float s1 = __expf(-d2 * INV1);
        const float s2 = __expf(-d2 * INV2);
        float acc = bias2;
#pragma unroll
        for (int j = 0; j < 32; j++) {
            float h = s_b1[j];
            h = fmaf(s0, s_w1[j], h);
            h = fmaf(s1, s_w1[32 + j], h);
            h = fmaf(s2, s_w1[64 + j], h);
            h = fmaxf(h, 0.0f);
            acc = fmaf(h, s_w2[j], acc);
        }
        wv = acc;
    }

    float v = wv;
#pragma unroll
    for (int o = 16; o > 0; o >>= 1) v += __shfl_down_sync(0xffffffffu, v, o);
    if ((tid & 31) == 0) warp_sums[tid >> 5] = v;
    __syncthreads();
    if (tid == 0) {
        float s = 0.0f;
#pragma unroll
        for (int i = 0; i < 10; i++) s += warp_sums[i];
        s_total = s + 1e-8f;
    }
    __syncthreads();

    float wn = (c < C_) ? (wv / s_total) : 0.0f;
    __nv_bfloat16 h = __float2bfloat16(wn);
    __nv_bfloat16 l = __float2bfloat16(wn - __bfloat162float(h));
    const size_t o = ((size_t)b * M_ + m) * CP_ + c;   // c covers full CP_
    g_w_hi[o] = h;
    g_w_lo[o] = l;
}

// ---------------------------------------------------------------------------
// Kernel 2: mma.sync split-bf16 GEMM with cp.async double-buffered pipeline.
// CTA = (t-tile, b): D[128 m][128 t] = sum_k W[m,k] * X[k,t]
// 8 warps as 2(m) x 4(n); warp tile 64(m) x 32(t). 2 CTAs/SM.
// ---------------------------------------------------------------------------
__global__ void __launch_bounds__(256, 2) mrm_hmma_kernel(
    const float* __restrict__ x, float* __restrict__ out)
{
    extern __shared__ __align__(16) char smem[];
    const uint32_t sb = smem_u32(smem);

    const int b   = blockIdx.y;
    const int t0  = blockIdx.x * TN_;
    const int tid = threadIdx.x;
    const int lane = tid & 31;
    const int wid  = tid >> 5;
    const int warp_m = wid >> 2;        // 0..1
    const int warp_n = wid & 3;         // 0..3
    const int tl = tid & 127;           // converter row (t column)
    const int kg = tid >> 7;            // 0/1 (k half)

    const float* xb = x + (size_t)b * C_ * T_;
    const char* xrow_base = (const char*)(xb) + (size_t)t0 * 4;

    // cp.async thread assignments (4 A-chunks + 4 X-chunks per thread)
    // A: chunk c in [0,1024): tile=c>>9 (hi/lo), row=(c&511)>>2, j=c&3
    // X: chunk c in [0,1024): k=c>>5, j=c&31
    const __nv_bfloat16* gwh = g_w_hi + (size_t)b * M_ * CP_;
    const __nv_bfloat16* gwl = g_w_lo + (size_t)b * M_ * CP_;

    // ldmatrix per-thread source coords
    const int lr  = lane & 7;
    const int sel = lane >> 3;          // 0..3
    const int a_row = warp_m * 64 + lr + (sel & 1) * 8;
    const int a_col = (sel >> 1) * 16;
    const int b_row = warp_n * 32 + lr + (sel >> 1) * 8;
    const int b_col = (sel & 1) * 16;

    float acc[4][4][4];
#pragma unroll
    for (int i = 0; i < 4; i++)
#pragma unroll
        for (int j = 0; j < 4; j++)
#pragma unroll
            for (int q = 0; q < 4; q++) acc[i][j][q] = 0.0f;

    // ---- cp.async issue helper (macro-ish lambda)
    auto issue_chunk = [&](int chunk, int s) {
        const int k0 = chunk * KC_;
#pragma unroll
        for (int r = 0; r < 4; r++) {
            const int c = tid + r * 256;
            const int tile = c >> 9;
            const int idx  = c & 511;
            const int row  = idx >> 2;
            const int j    = idx & 3;
            const __nv_bfloat16* src = (tile ? gwl : gwh) + (size_t)row * CP_ + k0 + j * 8;
            const uint32_t dst = sb + (tile ? OFF_AL(s) : OFF_AH(s)) + row * RS + j * 16;
            CP16(dst, src, 16);
        }
#pragma unroll
        for (int r = 0; r < 4; r++) {
            const int c = tid + r * 256;
            const int k = c >> 5;
            const int j = c & 31;
            const char* src = xrow_base + (size_t)(k0 + k) * (T_ * 4) + j * 16;
            const uint32_t dst = sb + OFF_XF(s) + k * 512 + j * 16;
            const uint32_t sz = ((k0 + k) < C_ && (t0 + j * 4) < T_) ? 16u : 0u;
            CP16(dst, src, sz);
        }
        CP_COMMIT();
    };

    // ---- prologue: chunks 0 and 1 in flight
    issue_chunk(0, 0);
    issue_chunk(1, 1);

    for (int i = 0; i < NCHUNK; i++) {
        const int s = i & 1;

        if (i == NCHUNK - 1) asm volatile("cp.async.wait_group 0;" ::: "memory");
        else                 asm volatile("cp.async.wait_group 1;" ::: "memory");
        __syncthreads();                      // chunk i resident, MMA(i-1) done

        // ---- convert staged fp32 X -> B_hi / B_lo bf16 tiles
        {
            const uint32_t xbase = sb + OFF_XF(s) + kg * (16 * 512) + tl * 4;
            float v[16];
#pragma unroll
            for (int j = 0; j < 16; j++) {
                asm volatile("ld.shared.f32 %0, [%1];" : "=f"(v[j]) : "r"(xbase + j * 512));
            }
            uint32_t hi[8], lo[8];
#pragma unroll
            for (int q = 0; q < 8; q++) {
                float v0 = v[2 * q], v1 = v[2 * q + 1];
                __nv_bfloat16 h0 = __float2bfloat16(v0);
                __nv_bfloat16 h1 = __float2bfloat16(v1);
                float l0 = v0 - __bfloat162float(h0);
                float l1 = v1 - __bfloat162float(h1);
                hi[q] = (uint32_t)__bfloat16_as_ushort(h0)
                      | ((uint32_t)__bfloat16_as_ushort(h1) << 16);
                __nv_bfloat16 g0 = __float2bfloat16(l0);
                __nv_bfloat16 g1 = __float2bfloat16(l1);
                lo[q] = (uint32_t)__bfloat16_as_ushort(g0)
                      | ((uint32_t)__bfloat16_as_ushort(g1) << 16);
            }
            const uint32_t boff = tl * RS + kg * 32;
            uint4 vh0 = make_uint4(hi[0], hi[1], hi[2], hi[3]);
            uint4 vh1 = make_uint4(hi[4], hi[5], hi[6], hi[7]);
            uint4 vl0 = make_uint4(lo[0], lo[1], lo[2], lo[3]);
            uint4 vl1 = make_uint4(lo[4], lo[5], lo[6], lo[7]);
            STS16(sb + OFF_BH + boff,      vh0);
            STS16(sb + OFF_BH + boff + 16, vh1);
            STS16(sb + OFF_BL + boff,      vl0);
            STS16(sb + OFF_BL + boff + 16, vl1);
        }
        __syncthreads();                      // B tiles ready

        // ---- MMA over the 2 k16 steps of this chunk
        const uint32_t sAh = sb + OFF_AH(s), sAl = sb + OFF_AL(s);
        const uint32_t sBh = sb + OFF_BH,   sBl = sb + OFF_BL;
#pragma unroll
        for (int ks = 0; ks < 2; ks++) {
            uint32_t af[4][4], bh[2][4], bl[2][4];
            const uint32_t acol = ks * 32 + a_col;
            const uint32_t bcol = ks * 32 + b_col;
#pragma unroll
            for (int g = 0; g < 2; g++) {
                LDSM4(bh[g], sBh + (uint32_t)(b_row + g * 16) * RS + bcol);
                LDSM4(bl[g], sBl + (uint32_t)(b_row + g * 16) * RS + bcol);
            }
#pragma unroll
            for (int mf = 0; mf < 4; mf++)
                LDSM4(af[mf], sAh + (uint32_t)(a_row + mf * 16) * RS + acol);
#pragma unroll
            for (int mf = 0; mf < 4; mf++)
#pragma unroll
                for (int nf = 0; nf < 4; nf++) {
                    const int g = nf >> 1, s2 = (nf & 1) * 2;
                    MMA_BF16(acc[mf][nf], af[mf], bh[g][s2], bh[g][s2 + 1]);
                    MMA_BF16(acc[mf][nf], af[mf], bl[g][s2], bl[g][s2 + 1]);
                }
#pragma unroll
            for (int mf = 0; mf < 4; mf++)
                LDSM4(af[mf], sAl + (uint32_t)(a_row + mf * 16) * RS + acol);
#pragma unroll
            for (int mf = 0; mf < 4; mf++)
#pragma unroll
                for (int nf = 0; nf < 4; nf++) {
                    const int g = nf >> 1, s2 = (nf & 1) * 2;
                    MMA_BF16(acc[mf][nf], af[mf], bh[g][s2], bh[g][s2 + 1]);
                }
        }
        __syncthreads();                      // stage s free for refill

        if (i + 2 < NCHUNK) issue_chunk(i + 2, s);
    }

    // ---- epilogue: direct global stores (T_ % 32 == 0 so warp tiles all-or-nothing)
    if (t0 + warp_n * 32 < T_) {
        const int mb = warp_m * 64 + (lane >> 2);
        const int cb = t0 + warp_n * 32 + (lane & 3) * 2;
#pragma unroll
        for (int mf = 0; mf < 4; mf++) {
#pragma unroll
            for (int nf = 0; nf < 4; nf++) {
                const int m = mb + mf * 16;
                const int t = cb + nf * 8;
                float* o0 = out + ((size_t)b * M_ + m) * T_ + t;
                float* o1 = out + ((size_t)b * M_ + m + 8) * T_ + t;
                *(float2*)o0 = make_float2(acc[mf][nf][0], acc[mf][nf][1]);
                *(float2*)o1 = make_float2(acc[mf][nf][2], acc[mf][nf][3]);
            }
        }
    }
}

// ---------------------------------------------------------------------------
extern "C" void kernel_launch(void* const* d_in, const int* in_sizes, int n_in,
                              void* d_out, int out_size) {
    const float* x    = (const float*)d_in[0];
    const float* pos  = (const float*)d_in[1];
    const float* tpos = (const float*)d_in[2];
    const float* w1   = (const float*)d_in[3];
    const float* b1   = (const float*)d_in[4];
    const float* w2   = (const float*)d_in[5];
    const float* b2   = (const float*)d_in[6];
    float* out = (float*)d_out;

    static int smem_set = 0;
    if (!smem_set) {
        cudaFuncSetAttribute(mrm_hmma_kernel,
                             cudaFuncAttributeMaxDynamicSharedMemorySize, SMEM_TOTAL);
        smem_set = 1;
    }

    mrm_weights_kernel<<<B_ * M_, CP_>>>(pos, tpos, w1, b1, w2, b2);

    dim3 grid((T_ + TN_ - 1) / TN_, B_);   // 32 x 16 = 512 CTAs
    mrm_hmma_kernel<<<grid, 256, SMEM_TOTAL>>>(x, out);
}